// round 8
// baseline (speedup 1.0000x reference)
#include <cuda_runtime.h>

#define NMAX 50000
#define EMAX 800000
#define HD   64
#define FIN  128
#define NHEADS 4

// ---------------- scratch (static device memory; no allocs) ----------------
__device__ float    d_h   [NMAX * HD];           // GCN pre-agg / post-relu features
__device__ float    d_h2  [NMAX * HD];           // GCN aggregation accumulator
__device__ float    d_hg  [NMAX * NHEADS * HD];  // GAT transformed features [N,4,64]
__device__ float    d_asrc[NMAX * NHEADS];
__device__ float    d_adst[NMAX * NHEADS];
__device__ unsigned d_emax[NMAX * NHEADS];       // ordered-uint float max keys
__device__ float    d_den [NMAX * NHEADS];       // softmax denominators
__device__ float    d_alpha[EMAX * NHEADS];      // per-edge attention weights
__device__ float    d_hga [NMAX * HD];           // GAT aggregation (head-mean)
__device__ float    d_h3  [NMAX * HD];           // post-GAT features
__device__ float    d_mean[NMAX * HD];           // SAGE sum accumulator
__device__ float    d_cnt [NMAX];                // in-degree (no self loops)
__device__ float    d_dinv[NMAX];                // rsqrt(deg+1)
__device__ int      d_row32[EMAX];               // validated edge sources
__device__ int      d_col32[EMAX];               // validated edge targets
__device__ float    d_nrm [EMAX];                // per-edge GCN norm dinv[r]*dinv[c]

// ---------------- helpers ----------------
__device__ __forceinline__ float lrelu(float x) { return x > 0.f ? x : 0.2f * x; }

// monotone float <-> uint key for atomicMax on floats
__device__ __forceinline__ unsigned f2key(float f) {
    unsigned u = __float_as_uint(f);
    return (u & 0x80000000u) ? ~u : (u | 0x80000000u);
}
__device__ __forceinline__ float key2f(unsigned k) {
    return (k & 0x80000000u) ? __uint_as_float(k & 0x7fffffffu) : __uint_as_float(~k);
}

// ---------------- kernels ----------------

// zero atomic accumulators: mean[N*64]
__global__ void k_zero_mean(int n) {
    int total = n * HD;
    int i = blockIdx.x * blockDim.x + threadIdx.x;
    if (i < total) d_mean[i] = 0.f;
}

// zero cnt[N]
__global__ void k_zero_cnt(int n) {
    int i = blockIdx.x * blockDim.x + threadIdx.x;
    if (i < n) d_cnt[i] = 0.f;
}

// edge_index is INT32 (JAX x64 disabled -> int64 becomes int32).
// Copy + validate + in-degree count. Invalid indices are clamped to node 0
// (defensive; reference data is always in range).
__global__ void k_edges32(const int* __restrict__ row0,
                          const int* __restrict__ col0, int e, int n) {
    int i = blockIdx.x * blockDim.x + threadIdx.x;
    if (i < e) {
        int r = row0[i];
        int c = col0[i];
        if ((unsigned)r >= (unsigned)n) r = 0;
        if ((unsigned)c >= (unsigned)n) c = 0;
        d_row32[i] = r;
        d_col32[i] = c;
        atomicAdd(&d_cnt[c], 1.f);
    }
}

__global__ void k_dinv(int n) {
    int i = blockIdx.x * blockDim.x + threadIdx.x;
    if (i < n) d_dinv[i] = rsqrtf(d_cnt[i] + 1.0f);
}

// per-edge GCN normalization factor
__global__ void k_nrm(int e) {
    int i = blockIdx.x * blockDim.x + threadIdx.x;
    if (i < e) d_nrm[i] = d_dinv[d_row32[i]] * d_dinv[d_col32[i]];
}

// generic small GEMM body: out[n,M] = A[n,K] @ W[K,M]   (no bias)
// blockDim = JT*SG; each thread: RPT rows x CPT cols register tile.
// Called only from __global__ wrappers so device-global buffers are
// referenced in DEVICE code, never passed from host.
template <int K, int M, int JT, int CPT, int SG, int RPT>
__device__ __forceinline__ void gemm_body(const float* __restrict__ A,
                                          const float* __restrict__ W,
                                          float* __restrict__ out, int n) {
    const int ROWS = SG * RPT;
    __shared__ float xs[ROWS][K];
    int tid = threadIdx.x;
    int j0  = tid % JT;
    int sg  = tid / JT;
    for (long long base = (long long)blockIdx.x * ROWS; base < n;
         base += (long long)gridDim.x * ROWS) {
        __syncthreads();
        for (int i = tid; i < ROWS * K; i += JT * SG) {
            long long row = base + i / K;
            xs[i / K][i % K] = (row < n) ? A[row * K + (i % K)] : 0.f;
        }
        __syncthreads();
        float acc[RPT][CPT];
#pragma unroll
        for (int r = 0; r < RPT; r++)
#pragma unroll
            for (int c = 0; c < CPT; c++) acc[r][c] = 0.f;
#pragma unroll 8
        for (int k = 0; k < K; k++) {
            float wv[CPT];
#pragma unroll
            for (int c = 0; c < CPT; c++) wv[c] = __ldg(&W[k * M + j0 + c * JT]);
#pragma unroll
            for (int r = 0; r < RPT; r++) {
                float xv = xs[sg * RPT + r][k];
#pragma unroll
                for (int c = 0; c < CPT; c++) acc[r][c] += xv * wv[c];
            }
        }
#pragma unroll
        for (int r = 0; r < RPT; r++) {
            long long row = base + sg * RPT + r;
            if (row < n) {
#pragma unroll
                for (int c = 0; c < CPT; c++)
                    out[row * M + j0 + c * JT] = acc[r][c];
            }
        }
    }
}

// GCN input GEMM: d_h = x @ W1   (x: [N,128], W1: [128,64])
__global__ void k_gemm_gcn(const float* __restrict__ x,
                           const float* __restrict__ W1, int n) {
    gemm_body<FIN, HD, 32, 2, 8, 8>(x, W1, d_h, n);
}

// GAT transform GEMM: d_hg = d_h @ Wg   (d_h: [N,64], Wg: [64,256])
__global__ void k_gemm_gat(const float* __restrict__ Wg, int n) {
    gemm_body<HD, NHEADS * HD, 64, 4, 4, 8>(d_h, Wg, d_hg, n);
}

// h2[i] = dinv[i]^2 * h[i]  (GCN self-loop term)
__global__ void k_h2init(int n) {
    int total = n * HD;
    int i = blockIdx.x * blockDim.x + threadIdx.x;
    if (i < total) {
        int node = i >> 6;
        float dv = d_dinv[node];
        d_h2[i] = dv * dv * d_h[i];
    }
}

// GCN scatter: h2[c] += nrm[e] * h[r]
__global__ void k_gcn_scatter(int e) {
    int total = e * HD;
    for (int t = blockIdx.x * blockDim.x + threadIdx.x; t < total;
         t += gridDim.x * blockDim.x) {
        int ed = t >> 6, j = t & 63;
        int r = __ldg(&d_row32[ed]);
        int c = __ldg(&d_col32[ed]);
        float nrm = __ldg(&d_nrm[ed]);
        atomicAdd(&d_h2[c * HD + j], nrm * __ldg(&d_h[r * HD + j]));
    }
}

// h = relu(h2 + b1)
__global__ void k_relu_b1(const float* __restrict__ b1, int n) {
    int total = n * HD;
    int i = blockIdx.x * blockDim.x + threadIdx.x;
    if (i < total) d_h[i] = fmaxf(d_h2[i] + b1[i & 63], 0.f);
}

// per-(node,head) attention logits a_src/a_dst  (one warp each)
__global__ void k_att(const float* __restrict__ att_src,
                      const float* __restrict__ att_dst, int n) {
    long long w = (long long)(blockIdx.x * blockDim.x + threadIdx.x) >> 5;
    int lane = threadIdx.x & 31;
    long long total = (long long)n * NHEADS;
    long long stride = ((long long)gridDim.x * blockDim.x) >> 5;
    for (; w < total; w += stride) {
        int node = (int)(w >> 2), head = (int)(w & 3);
        const float* hgp = &d_hg[(long long)node * (NHEADS * HD) + head * HD];
        float s = hgp[lane] * __ldg(&att_src[head * HD + lane]) +
                  hgp[lane + 32] * __ldg(&att_src[head * HD + lane + 32]);
        float t = hgp[lane] * __ldg(&att_dst[head * HD + lane]) +
                  hgp[lane + 32] * __ldg(&att_dst[head * HD + lane + 32]);
#pragma unroll
        for (int o = 16; o; o >>= 1) {
            s += __shfl_down_sync(0xffffffffu, s, o);
            t += __shfl_down_sync(0xffffffffu, t, o);
        }
        if (lane == 0) { d_asrc[w] = s; d_adst[w] = t; }
    }
}

// emax init with self-loop value
__global__ void k_emax_init(int n) {
    int i = blockIdx.x * blockDim.x + threadIdx.x;
    if (i < n * NHEADS) d_emax[i] = f2key(lrelu(d_asrc[i] + d_adst[i]));
}

__global__ void k_emax_edges(int e) {
    int i = blockIdx.x * blockDim.x + threadIdx.x;
    if (i < e) {
        int r = d_row32[i], c = d_col32[i];
#pragma unroll
        for (int h = 0; h < NHEADS; h++) {
            float v = lrelu(d_asrc[r * NHEADS + h] + d_adst[c * NHEADS + h]);
            atomicMax(&d_emax[c * NHEADS + h], f2key(v));
        }
    }
}

// denom = exp(self - max)   (direct write: initializes)
__global__ void k_den_self(int n) {
    int i = blockIdx.x * blockDim.x + threadIdx.x;
    if (i < n * NHEADS) {
        float ev = lrelu(d_asrc[i] + d_adst[i]);
        d_den[i] = expf(ev - key2f(d_emax[i]));
    }
}

__global__ void k_den_edges(int e) {
    int i = blockIdx.x * blockDim.x + threadIdx.x;
    if (i < e) {
        int r = d_row32[i], c = d_col32[i];
#pragma unroll
        for (int h = 0; h < NHEADS; h++) {
            float v = lrelu(d_asrc[r * NHEADS + h] + d_adst[c * NHEADS + h]);
            atomicAdd(&d_den[c * NHEADS + h], expf(v - key2f(d_emax[c * NHEADS + h])));
        }
    }
}

// per-edge alpha (computed once, broadcast in scatter)
__global__ void k_alpha(int e) {
    int i = blockIdx.x * blockDim.x + threadIdx.x;
    if (i < e) {
        int r = d_row32[i], c = d_col32[i];
#pragma unroll
        for (int h = 0; h < NHEADS; h++) {
            float v = lrelu(d_asrc[r * NHEADS + h] + d_adst[c * NHEADS + h]);
            d_alpha[i * NHEADS + h] =
                expf(v - key2f(d_emax[c * NHEADS + h])) / d_den[c * NHEADS + h];
        }
    }
}

// hga init with self-loop contribution: 0.25 * sum_h alpha_self_h * hg[i,h,:]
__global__ void k_hga_init(int n) {
    int total = n * HD;
    int i = blockIdx.x * blockDim.x + threadIdx.x;
    if (i < total) {
        int node = i >> 6, j = i & 63;
        float s = 0.f;
#pragma unroll
        for (int h = 0; h < NHEADS; h++) {
            float v = lrelu(d_asrc[node * NHEADS + h] + d_adst[node * NHEADS + h]);
            float a = expf(v - key2f(d_emax[node * NHEADS + h])) / d_den[node * NHEADS + h];
            s += a * d_hg[(long long)node * (NHEADS * HD) + h * HD + j];
        }
        d_hga[i] = 0.25f * s;
    }
}

// GAT scatter: hga[c,j] += 0.25 * sum_h alpha[e,h] * hg[r,h,j]
__global__ void k_gat_scatter(int e) {
    int total = e * HD;
    for (int t = blockIdx.x * blockDim.x + threadIdx.x; t < total;
         t += gridDim.x * blockDim.x) {
        int ed = t >> 6, j = t & 63;
        int r = __ldg(&d_row32[ed]);
        int c = __ldg(&d_col32[ed]);
        const float* hgp = &d_hg[(long long)r * (NHEADS * HD) + j];
        float s = __ldg(&d_alpha[ed * NHEADS + 0]) * __ldg(&hgp[0 * HD]) +
                  __ldg(&d_alpha[ed * NHEADS + 1]) * __ldg(&hgp[1 * HD]) +
                  __ldg(&d_alpha[ed * NHEADS + 2]) * __ldg(&hgp[2 * HD]) +
                  __ldg(&d_alpha[ed * NHEADS + 3]) * __ldg(&hgp[3 * HD]);
        atomicAdd(&d_hga[c * HD + j], 0.25f * s);
    }
}

// h3 = relu(hga + bg)
__global__ void k_relu_bg(const float* __restrict__ bg, int n) {
    int total = n * HD;
    int i = blockIdx.x * blockDim.x + threadIdx.x;
    if (i < total) d_h3[i] = fmaxf(d_hga[i] + bg[i & 63], 0.f);
}

// SAGE scatter (original edges, sum; mean later)
__global__ void k_sage_scatter(int e) {
    int total = e * HD;
    for (int t = blockIdx.x * blockDim.x + threadIdx.x; t < total;
         t += gridDim.x * blockDim.x) {
        int ed = t >> 6, j = t & 63;
        int r = __ldg(&d_row32[ed]);
        int c = __ldg(&d_col32[ed]);
        atomicAdd(&d_mean[c * HD + j], __ldg(&d_h3[r * HD + j]));
    }
}

// final: emb = mean@Wl + bl + h3@Wr ; heads ; write outputs
__global__ void k_final(const float* __restrict__ Wl, const float* __restrict__ bl,
                        const float* __restrict__ Wr,
                        const float* __restrict__ a1w, const float* __restrict__ a1b,
                        const float* __restrict__ a2w, const float* __restrict__ a2b,
                        const float* __restrict__ r1w, const float* __restrict__ r1b,
                        const float* __restrict__ r2w, const float* __restrict__ r2b,
                        float* __restrict__ out_emb, float* __restrict__ out_an,
                        float* __restrict__ out_risk, int n) {
    __shared__ float Wls[HD * HD], Wrs[HD * HD];
    __shared__ float ms[4][HD], hs[4][HD], embs[4][HD];
    int tid = threadIdx.x;
    for (int i = tid; i < HD * HD; i += blockDim.x) {
        Wls[i] = Wl[i];
        Wrs[i] = Wr[i];
    }
    int sub = tid >> 6, j = tid & 63;
    int lane = tid & 31, wp = tid >> 5;
    int nd = wp >> 1, hd = wp & 1;
    for (long long base = (long long)blockIdx.x * 4; base < n;
         base += (long long)gridDim.x * 4) {
        int node = (int)base + sub;
        __syncthreads();
        if (node < n) {
            float inv = 1.f / fmaxf(d_cnt[node], 1.f);
            ms[sub][j] = d_mean[node * HD + j] * inv;
            hs[sub][j] = d_h3[node * HD + j];
        }
        __syncthreads();
        if (node < n) {
            float acc = bl[j];
#pragma unroll 16
            for (int k = 0; k < HD; k++)
                acc += ms[sub][k] * Wls[k * HD + j] + hs[sub][k] * Wrs[k * HD + j];
            embs[sub][j] = acc;
            out_emb[(long long)node * HD + j] = acc;
        }
        __syncthreads();
        int node2 = (int)base + nd;
        if (node2 < n) {
            const float* W1p = hd ? r1w : a1w;
            float acc = hd ? __ldg(&r1b[lane]) : __ldg(&a1b[lane]);
#pragma unroll 16
            for (int k = 0; k < HD; k++)
                acc += embs[nd][k] * __ldg(&W1p[k * 32 + lane]);
            acc = fmaxf(acc, 0.f) * (hd ? __ldg(&r2w[lane]) : __ldg(&a2w[lane]));
#pragma unroll
            for (int o = 16; o; o >>= 1) acc += __shfl_down_sync(0xffffffffu, acc, o);
            if (lane == 0) {
                float b2 = hd ? __ldg(&r2b[0]) : __ldg(&a2b[0]);
                float v = 1.f / (1.f + expf(-(acc + b2)));
                if (hd) out_risk[node2] = v;
                else    out_an[node2] = v;
            }
        }
    }
}

// ---------------- launcher ----------------
extern "C" void kernel_launch(void* const* d_in, const int* in_sizes, int n_in,
                              void* d_out, int out_size) {
    const float* x   = (const float*)d_in[0];
    const int*   ei  = (const int*)d_in[1];   // int32! (JAX x64 disabled)
    const float* W1  = (const float*)d_in[2];
    const float* b1  = (const float*)d_in[3];
    const float* Wg  = (const float*)d_in[4];
    const float* ats = (const float*)d_in[5];
    const float* atd = (const float*)d_in[6];
    const float* bg  = (const float*)d_in[7];
    const float* Wl  = (const float*)d_in[8];
    const float* bl  = (const float*)d_in[9];
    const float* Wr  = (const float*)d_in[10];
    const float* a1w = (const float*)d_in[11];
    const float* a1b = (const float*)d_in[12];
    const float* a2w = (const float*)d_in[13];
    const float* a2b = (const float*)d_in[14];
    const float* r1w = (const float*)d_in[15];
    const float* r1b = (const float*)d_in[16];
    const float* r2w = (const float*)d_in[17];
    const float* r2b = (const float*)d_in[18];

    int n = in_sizes[0] / FIN;
    int e = in_sizes[1] / 2;
    const int* row0 = ei;
    const int* col0 = ei + e;

    float* out      = (float*)d_out;
    float* out_emb  = out;
    float* out_an   = out + (long long)n * HD;
    float* out_risk = out_an + n;

    const int B = 256;
    int gNH  = (n * HD + B - 1) / B;        // elementwise over N*64
    int gN   = (n + B - 1) / B;
    int gE   = (e + B - 1) / B;
    int gEH  = (e * HD + B - 1) / B;        // scatter over E*64
    int gNH4 = (n * NHEADS + B - 1) / B;

    // degrees + edge preprocessing
    k_zero_mean<<<gNH, B>>>(n);
    k_zero_cnt<<<gN, B>>>(n);
    k_edges32<<<gE, B>>>(row0, col0, e, n);
    k_dinv<<<gN, B>>>(n);
    k_nrm<<<gE, B>>>(e);

    // GCN
    k_gemm_gcn<<<(n + 63) / 64, 256>>>(x, W1, n);
    k_h2init<<<gNH, B>>>(n);
    k_gcn_scatter<<<gEH, B>>>(e);
    k_relu_b1<<<gNH, B>>>(b1, n);

    // GAT
    k_gemm_gat<<<(n + 31) / 32, 256>>>(Wg, n);
    k_att<<<(n * NHEADS * 32 + B - 1) / B, B>>>(ats, atd, n);
    k_emax_init<<<gNH4, B>>>(n);
    k_emax_edges<<<gE, B>>>(e);
    k_den_self<<<gNH4, B>>>(n);
    k_den_edges<<<gE, B>>>(e);
    k_alpha<<<gE, B>>>(e);
    k_hga_init<<<gNH, B>>>(n);
    k_gat_scatter<<<gEH, B>>>(e);
    k_relu_bg<<<gNH, B>>>(bg, n);

    // SAGE
    k_sage_scatter<<<gEH, B>>>(e);

    // emb + heads
    k_final<<<(n + 3) / 4, B>>>(Wl, bl, Wr, a1w, a1b, a2w, a2b,
                                r1w, r1b, r2w, r2b,
                                out_emb, out_an, out_risk, n);
}

// round 9
// speedup vs baseline: 1.7268x; 1.7268x over previous
#include <cuda_runtime.h>

#define NMAX 50000
#define EMAX 800000
#define HD   64
#define FIN  128
#define NHEADS 4

// ---------------- scratch (static device memory; no allocs) ----------------
__device__ __align__(16) float    d_h   [NMAX * HD];          // GCN: dinv-scaled xW1, then post-relu h
__device__ __align__(16) float    d_h2  [NMAX * HD];          // GCN aggregation accumulator
__device__ __align__(16) float    d_hg  [NMAX * NHEADS * HD]; // GAT features [N,4,64]
__device__ __align__(16) float    d_asrc[NMAX * NHEADS];
__device__ __align__(16) float    d_adst[NMAX * NHEADS];
__device__ __align__(16) unsigned d_emax[NMAX * NHEADS];      // ordered-uint float max keys
__device__ __align__(16) float    d_den [NMAX * NHEADS];      // softmax denom -> 0.25/denom
__device__ __align__(16) float    d_alpha[EMAX * NHEADS];     // per-edge exp values
__device__ __align__(16) float    d_hga [NMAX * HD];          // GAT aggregation
__device__ __align__(16) float    d_h3  [NMAX * HD];          // post-GAT features
__device__ __align__(16) float    d_mean[NMAX * HD];          // SAGE sum accumulator
__device__ float    d_cnt [NMAX];                             // in-degree (no self loops)
__device__ float    d_dinv[NMAX];                             // rsqrt(deg+1)
__device__ int      d_row32[EMAX];
__device__ int      d_col32[EMAX];

// ---------------- helpers ----------------
__device__ __forceinline__ float lrelu(float x) { return x > 0.f ? x : 0.2f * x; }

__device__ __forceinline__ unsigned f2key(float f) {
    unsigned u = __float_as_uint(f);
    return (u & 0x80000000u) ? ~u : (u | 0x80000000u);
}
__device__ __forceinline__ float key2f(unsigned k) {
    return (k & 0x80000000u) ? __uint_as_float(k & 0x7fffffffu) : __uint_as_float(~k);
}

// vector reduction (no return) — sm_90+: 1 instruction for 4 lanes of atomicAdd
__device__ __forceinline__ void red_add_v4(float4* p, float4 v) {
    asm volatile("red.global.add.v4.f32 [%0], {%1, %2, %3, %4};"
                 :: "l"(p), "f"(v.x), "f"(v.y), "f"(v.z), "f"(v.w) : "memory");
}

// ---------------- kernels ----------------

__global__ void k_zero_mean(int n) {           // zero SAGE accumulator (vectorized)
    int total = n * (HD / 4);
    int i = blockIdx.x * blockDim.x + threadIdx.x;
    if (i < total) reinterpret_cast<float4*>(d_mean)[i] = make_float4(0.f, 0.f, 0.f, 0.f);
}

__global__ void k_zero_cnt(int n) {
    int i = blockIdx.x * blockDim.x + threadIdx.x;
    if (i < n) d_cnt[i] = 0.f;
}

// edge_index is INT32 (JAX x64 disabled). Copy + validate + in-degree count.
__global__ void k_edges32(const int* __restrict__ row0,
                          const int* __restrict__ col0, int e, int n) {
    int i = blockIdx.x * blockDim.x + threadIdx.x;
    if (i < e) {
        int r = row0[i];
        int c = col0[i];
        if ((unsigned)r >= (unsigned)n) r = 0;
        if ((unsigned)c >= (unsigned)n) c = 0;
        d_row32[i] = r;
        d_col32[i] = c;
        atomicAdd(&d_cnt[c], 1.f);
    }
}

__global__ void k_dinv(int n) {
    int i = blockIdx.x * blockDim.x + threadIdx.x;
    if (i < n) d_dinv[i] = rsqrtf(d_cnt[i] + 1.0f);
}

// GCN GEMM with fused epilogue: v = dinv[row] * (x@W1); d_h = v; d_h2 = v (self-term init)
__global__ void k_gemm_gcn(const float* __restrict__ A, const float* __restrict__ W, int n) {
    const int K = FIN, M = HD, JT = 32, CPT = 2, SG = 8, RPT = 8;
    const int ROWS = SG * RPT;
    __shared__ float xs[ROWS][K];
    int tid = threadIdx.x;
    int j0  = tid % JT;
    int sg  = tid / JT;
    for (long long base = (long long)blockIdx.x * ROWS; base < n;
         base += (long long)gridDim.x * ROWS) {
        __syncthreads();
        for (int i = tid; i < ROWS * K; i += JT * SG) {
            long long row = base + i / K;
            xs[i / K][i % K] = (row < n) ? A[row * K + (i % K)] : 0.f;
        }
        __syncthreads();
        float acc[RPT][CPT];
#pragma unroll
        for (int r = 0; r < RPT; r++)
#pragma unroll
            for (int c = 0; c < CPT; c++) acc[r][c] = 0.f;
#pragma unroll 8
        for (int k = 0; k < K; k++) {
            float wv[CPT];
#pragma unroll
            for (int c = 0; c < CPT; c++) wv[c] = __ldg(&W[k * M + j0 + c * JT]);
#pragma unroll
            for (int r = 0; r < RPT; r++) {
                float xv = xs[sg * RPT + r][k];
#pragma unroll
                for (int c = 0; c < CPT; c++) acc[r][c] += xv * wv[c];
            }
        }
#pragma unroll
        for (int r = 0; r < RPT; r++) {
            long long row = base + sg * RPT + r;
            if (row < n) {
                float dv = __ldg(&d_dinv[row]);
#pragma unroll
                for (int c = 0; c < CPT; c++) {
                    float v = acc[r][c] * dv;
                    long long idx = row * M + j0 + c * JT;
                    d_h[idx]  = v;
                    d_h2[idx] = v;
                }
            }
        }
    }
}

// GAT transform GEMM: d_hg = d_h @ Wg
__global__ void k_gemm_gat(const float* __restrict__ Wg, int n) {
    const int K = HD, M = NHEADS * HD, JT = 64, CPT = 4, SG = 4, RPT = 8;
    const int ROWS = SG * RPT;
    __shared__ float xs[ROWS][K];
    const float* A = d_h;
    float* out = d_hg;
    int tid = threadIdx.x;
    int j0  = tid % JT;
    int sg  = tid / JT;
    for (long long base = (long long)blockIdx.x * ROWS; base < n;
         base += (long long)gridDim.x * ROWS) {
        __syncthreads();
        for (int i = tid; i < ROWS * K; i += JT * SG) {
            long long row = base + i / K;
            xs[i / K][i % K] = (row < n) ? A[row * K + (i % K)] : 0.f;
        }
        __syncthreads();
        float acc[RPT][CPT];
#pragma unroll
        for (int r = 0; r < RPT; r++)
#pragma unroll
            for (int c = 0; c < CPT; c++) acc[r][c] = 0.f;
#pragma unroll 8
        for (int k = 0; k < K; k++) {
            float wv[CPT];
#pragma unroll
            for (int c = 0; c < CPT; c++) wv[c] = __ldg(&Wg[k * M + j0 + c * JT]);
#pragma unroll
            for (int r = 0; r < RPT; r++) {
                float xv = xs[sg * RPT + r][k];
#pragma unroll
                for (int c = 0; c < CPT; c++) acc[r][c] += xv * wv[c];
            }
        }
#pragma unroll
        for (int r = 0; r < RPT; r++) {
            long long row = base + sg * RPT + r;
            if (row < n) {
#pragma unroll
                for (int c = 0; c < CPT; c++)
                    out[row * M + j0 + c * JT] = acc[r][c];
            }
        }
    }
}

// GCN scatter (float4): h2[c] += hs[r]   (hs = dinv*xW1 already in d_h)
__global__ void k_gcn_scatter(int e) {
    int total = e * (HD / 4);
    int t = blockIdx.x * blockDim.x + threadIdx.x;
    if (t < total) {
        int ed = t >> 4, q = t & 15;
        int r = __ldg(&d_row32[ed]);
        int c = __ldg(&d_col32[ed]);
        float4 v = reinterpret_cast<const float4*>(d_h)[r * 16 + q];
        red_add_v4(&reinterpret_cast<float4*>(d_h2)[c * 16 + q], v);
    }
}

// h = relu(dinv[c]*h2 + b1)
__global__ void k_relu_b1(const float* __restrict__ b1, int n) {
    int total = n * HD;
    int i = blockIdx.x * blockDim.x + threadIdx.x;
    if (i < total) d_h[i] = fmaxf(d_dinv[i >> 6] * d_h2[i] + b1[i & 63], 0.f);
}

// per-(node,head) attention logits (one warp each)
__global__ void k_att(const float* __restrict__ att_src,
                      const float* __restrict__ att_dst, int n) {
    long long w = (long long)(blockIdx.x * blockDim.x + threadIdx.x) >> 5;
    int lane = threadIdx.x & 31;
    long long total = (long long)n * NHEADS;
    long long stride = ((long long)gridDim.x * blockDim.x) >> 5;
    for (; w < total; w += stride) {
        int node = (int)(w >> 2), head = (int)(w & 3);
        const float* hgp = &d_hg[(long long)node * (NHEADS * HD) + head * HD];
        float s = hgp[lane] * __ldg(&att_src[head * HD + lane]) +
                  hgp[lane + 32] * __ldg(&att_src[head * HD + lane + 32]);
        float t = hgp[lane] * __ldg(&att_dst[head * HD + lane]) +
                  hgp[lane + 32] * __ldg(&att_dst[head * HD + lane + 32]);
#pragma unroll
        for (int o = 16; o; o >>= 1) {
            s += __shfl_down_sync(0xffffffffu, s, o);
            t += __shfl_down_sync(0xffffffffu, t, o);
        }
        if (lane == 0) { d_asrc[w] = s; d_adst[w] = t; }
    }
}

__global__ void k_emax_init(int n) {
    int i = blockIdx.x * blockDim.x + threadIdx.x;
    if (i < n * NHEADS) d_emax[i] = f2key(lrelu(d_asrc[i] + d_adst[i]));
}

__global__ void k_emax_edges(int e) {
    int i = blockIdx.x * blockDim.x + threadIdx.x;
    if (i < e) {
        int r = d_row32[i], c = d_col32[i];
#pragma unroll
        for (int h = 0; h < NHEADS; h++) {
            float v = lrelu(d_asrc[r * NHEADS + h] + d_adst[c * NHEADS + h]);
            atomicMax(&d_emax[c * NHEADS + h], f2key(v));
        }
    }
}

// denom init = exp(self - max)
__global__ void k_den_self(int n) {
    int i = blockIdx.x * blockDim.x + threadIdx.x;
    if (i < n * NHEADS) {
        float ev = lrelu(d_asrc[i] + d_adst[i]);
        d_den[i] = expf(ev - key2f(d_emax[i]));
    }
}

// per-edge ex: store to d_alpha AND accumulate into denom
__global__ void k_den_edges(int e) {
    int i = blockIdx.x * blockDim.x + threadIdx.x;
    if (i < e) {
        int r = d_row32[i], c = d_col32[i];
        float4 ex;
        {
            float v = lrelu(d_asrc[r * NHEADS + 0] + d_adst[c * NHEADS + 0]);
            ex.x = expf(v - key2f(d_emax[c * NHEADS + 0]));
            v = lrelu(d_asrc[r * NHEADS + 1] + d_adst[c * NHEADS + 1]);
            ex.y = expf(v - key2f(d_emax[c * NHEADS + 1]));
            v = lrelu(d_asrc[r * NHEADS + 2] + d_adst[c * NHEADS + 2]);
            ex.z = expf(v - key2f(d_emax[c * NHEADS + 2]));
            v = lrelu(d_asrc[r * NHEADS + 3] + d_adst[c * NHEADS + 3]);
            ex.w = expf(v - key2f(d_emax[c * NHEADS + 3]));
        }
        reinterpret_cast<float4*>(d_alpha)[i] = ex;
        atomicAdd(&d_den[c * NHEADS + 0], ex.x);
        atomicAdd(&d_den[c * NHEADS + 1], ex.y);
        atomicAdd(&d_den[c * NHEADS + 2], ex.z);
        atomicAdd(&d_den[c * NHEADS + 3], ex.w);
    }
}

// invert denominators once: d_den = 0.25/den (folds the head-mean 1/4)
__global__ void k_deninv(int n) {
    int i = blockIdx.x * blockDim.x + threadIdx.x;
    if (i < n * NHEADS) d_den[i] = 0.25f / d_den[i];
}

// hga init (float4): self contribution, weights recomputed per node
__global__ void k_hga_init(int n) {
    int total = n * (HD / 4);
    int t = blockIdx.x * blockDim.x + threadIdx.x;
    if (t < total) {
        int node = t >> 4, q = t & 15;
        const float4 as = reinterpret_cast<const float4*>(d_asrc)[node];
        const float4 ad = reinterpret_cast<const float4*>(d_adst)[node];
        const uint4  mk = reinterpret_cast<const uint4*>(d_emax)[node];
        const float4 dn = reinterpret_cast<const float4*>(d_den)[node];  // 0.25/den
        float wx = expf(lrelu(as.x + ad.x) - key2f(mk.x)) * dn.x;
        float wy = expf(lrelu(as.y + ad.y) - key2f(mk.y)) * dn.y;
        float wz = expf(lrelu(as.z + ad.z) - key2f(mk.z)) * dn.z;
        float ww = expf(lrelu(as.w + ad.w) - key2f(mk.w)) * dn.w;
        const float4* hg4 = reinterpret_cast<const float4*>(d_hg);
        long long base = (long long)node * 64;
        float4 a = hg4[base + 0 * 16 + q];
        float4 b = hg4[base + 1 * 16 + q];
        float4 cc = hg4[base + 2 * 16 + q];
        float4 dd = hg4[base + 3 * 16 + q];
        float4 s;
        s.x = wx * a.x + wy * b.x + wz * cc.x + ww * dd.x;
        s.y = wx * a.y + wy * b.y + wz * cc.y + ww * dd.y;
        s.z = wx * a.z + wy * b.z + wz * cc.z + ww * dd.z;
        s.w = wx * a.w + wy * b.w + wz * cc.w + ww * dd.w;
        reinterpret_cast<float4*>(d_hga)[node * 16 + q] = s;
    }
}

// GAT scatter (float4): hga[c] += sum_h (ex[e,h]*0.25/den[c,h]) * hg[r,h,:]
__global__ void k_gat_scatter(int e) {
    int total = e * (HD / 4);
    int t = blockIdx.x * blockDim.x + threadIdx.x;
    if (t < total) {
        int ed = t >> 4, q = t & 15;
        int r = __ldg(&d_row32[ed]);
        int c = __ldg(&d_col32[ed]);
        const float4 ex = reinterpret_cast<const float4*>(d_alpha)[ed];
        const float4 dn = reinterpret_cast<const float4*>(d_den)[c];   // 0.25/den
        float wx = ex.x * dn.x, wy = ex.y * dn.y, wz = ex.z * dn.z, ww = ex.w * dn.w;
        const float4* hg4 = reinterpret_cast<const float4*>(d_hg);
        long long base = (long long)r * 64;
        float4 a = hg4[base + 0 * 16 + q];
        float4 b = hg4[base + 1 * 16 + q];
        float4 cc = hg4[base + 2 * 16 + q];
        float4 dd = hg4[base + 3 * 16 + q];
        float4 s;
        s.x = wx * a.x + wy * b.x + wz * cc.x + ww * dd.x;
        s.y = wx * a.y + wy * b.y + wz * cc.y + ww * dd.y;
        s.z = wx * a.z + wy * b.z + wz * cc.z + ww * dd.z;
        s.w = wx * a.w + wy * b.w + wz * cc.w + ww * dd.w;
        red_add_v4(&reinterpret_cast<float4*>(d_hga)[c * 16 + q], s);
    }
}

// h3 = relu(hga + bg)
__global__ void k_relu_bg(const float* __restrict__ bg, int n) {
    int total = n * HD;
    int i = blockIdx.x * blockDim.x + threadIdx.x;
    if (i < total) d_h3[i] = fmaxf(d_hga[i] + bg[i & 63], 0.f);
}

// SAGE scatter (float4): mean[c] += h3[r]
__global__ void k_sage_scatter(int e) {
    int total = e * (HD / 4);
    int t = blockIdx.x * blockDim.x + threadIdx.x;
    if (t < total) {
        int ed = t >> 4, q = t & 15;
        int r = __ldg(&d_row32[ed]);
        int c = __ldg(&d_col32[ed]);
        float4 v = reinterpret_cast<const float4*>(d_h3)[r * 16 + q];
        red_add_v4(&reinterpret_cast<float4*>(d_mean)[c * 16 + q], v);
    }
}

// final: emb = mean@Wl + bl + h3@Wr ; MLP heads ; write outputs
__global__ void k_final(const float* __restrict__ Wl, const float* __restrict__ bl,
                        const float* __restrict__ Wr,
                        const float* __restrict__ a1w, const float* __restrict__ a1b,
                        const float* __restrict__ a2w, const float* __restrict__ a2b,
                        const float* __restrict__ r1w, const float* __restrict__ r1b,
                        const float* __restrict__ r2w, const float* __restrict__ r2b,
                        float* __restrict__ out_emb, float* __restrict__ out_an,
                        float* __restrict__ out_risk, int n) {
    __shared__ float Wls[HD * HD], Wrs[HD * HD];
    __shared__ float ms[4][HD], hs[4][HD], embs[4][HD];
    int tid = threadIdx.x;
    for (int i = tid; i < HD * HD; i += blockDim.x) {
        Wls[i] = Wl[i];
        Wrs[i] = Wr[i];
    }
    int sub = tid >> 6, j = tid & 63;
    int lane = tid & 31, wp = tid >> 5;
    int nd = wp >> 1, hd = wp & 1;
    for (long long base = (long long)blockIdx.x * 4; base < n;
         base += (long long)gridDim.x * 4) {
        int node = (int)base + sub;
        __syncthreads();
        if (node < n) {
            float inv = 1.f / fmaxf(d_cnt[node], 1.f);
            ms[sub][j] = d_mean[node * HD + j] * inv;
            hs[sub][j] = d_h3[node * HD + j];
        }
        __syncthreads();
        if (node < n) {
            float acc = bl[j];
#pragma unroll 16
            for (int k = 0; k < HD; k++)
                acc += ms[sub][k] * Wls[k * HD + j] + hs[sub][k] * Wrs[k * HD + j];
            embs[sub][j] = acc;
            out_emb[(long long)node * HD + j] = acc;
        }
        __syncthreads();
        int node2 = (int)base + nd;
        if (node2 < n) {
            const float* W1p = hd ? r1w : a1w;
            float acc = hd ? __ldg(&r1b[lane]) : __ldg(&a1b[lane]);
#pragma unroll 16
            for (int k = 0; k < HD; k++)
                acc += embs[nd][k] * __ldg(&W1p[k * 32 + lane]);
            acc = fmaxf(acc, 0.f) * (hd ? __ldg(&r2w[lane]) : __ldg(&a2w[lane]));
#pragma unroll
            for (int o = 16; o; o >>= 1) acc += __shfl_down_sync(0xffffffffu, acc, o);
            if (lane == 0) {
                float b2 = hd ? __ldg(&r2b[0]) : __ldg(&a2b[0]);
                float v = 1.f / (1.f + expf(-(acc + b2)));
                if (hd) out_risk[node2] = v;
                else    out_an[node2] = v;
            }
        }
    }
}

// ---------------- launcher ----------------
extern "C" void kernel_launch(void* const* d_in, const int* in_sizes, int n_in,
                              void* d_out, int out_size) {
    const float* x   = (const float*)d_in[0];
    const int*   ei  = (const int*)d_in[1];   // int32 (JAX x64 disabled)
    const float* W1  = (const float*)d_in[2];
    const float* b1  = (const float*)d_in[3];
    const float* Wg  = (const float*)d_in[4];
    const float* ats = (const float*)d_in[5];
    const float* atd = (const float*)d_in[6];
    const float* bg  = (const float*)d_in[7];
    const float* Wl  = (const float*)d_in[8];
    const float* bl  = (const float*)d_in[9];
    const float* Wr  = (const float*)d_in[10];
    const float* a1w = (const float*)d_in[11];
    const float* a1b = (const float*)d_in[12];
    const float* a2w = (const float*)d_in[13];
    const float* a2b = (const float*)d_in[14];
    const float* r1w = (const float*)d_in[15];
    const float* r1b = (const float*)d_in[16];
    const float* r2w = (const float*)d_in[17];
    const float* r2b = (const float*)d_in[18];

    int n = in_sizes[0] / FIN;
    int e = in_sizes[1] / 2;
    const int* row0 = ei;
    const int* col0 = ei + e;

    float* out      = (float*)d_out;
    float* out_emb  = out;
    float* out_an   = out + (long long)n * HD;
    float* out_risk = out_an + n;

    const int B = 256;
    int gNH  = (n * HD + B - 1) / B;
    int gN   = (n + B - 1) / B;
    int gE   = (e + B - 1) / B;
    int gE4  = (e * (HD / 4) + B - 1) / B;    // float4 scatter grids
    int gN4  = (n * (HD / 4) + B - 1) / B;
    int gNH4 = (n * NHEADS + B - 1) / B;

    // degrees + edge preprocessing
    k_zero_mean<<<gN4, B>>>(n);
    k_zero_cnt<<<gN, B>>>(n);
    k_edges32<<<gE, B>>>(row0, col0, e, n);
    k_dinv<<<gN, B>>>(n);

    // GCN (GEMM epilogue prescales by dinv and inits h2 with self term)
    k_gemm_gcn<<<(n + 63) / 64, 256>>>(x, W1, n);
    k_gcn_scatter<<<gE4, B>>>(e);
    k_relu_b1<<<gNH, B>>>(b1, n);

    // GAT
    k_gemm_gat<<<(n + 31) / 32, 256>>>(Wg, n);
    k_att<<<(n * NHEADS * 32 + B - 1) / B, B>>>(ats, atd, n);
    k_emax_init<<<gNH4, B>>>(n);
    k_emax_edges<<<gE, B>>>(e);
    k_den_self<<<gNH4, B>>>(n);
    k_den_edges<<<gE, B>>>(e);
    k_deninv<<<gNH4, B>>>(n);
    k_hga_init<<<gN4, B>>>(n);
    k_gat_scatter<<<gE4, B>>>(e);
    k_relu_bg<<<gNH, B>>>(bg, n);

    // SAGE
    k_sage_scatter<<<gE4, B>>>(e);

    // emb + heads
    k_final<<<(n + 3) / 4, B>>>(Wl, bl, Wr, a1w, a1b, a2w, a2b,
                                r1w, r1b, r2w, r2b,
                                out_emb, out_an, out_risk, n);
}

// round 10
// speedup vs baseline: 1.8654x; 1.0803x over previous
#include <cuda_runtime.h>

#define NMAX 50000
#define EMAX 800000
#define HD   64
#define FIN  128
#define NHEADS 4

// ---------------- scratch (static device memory; no allocs) ----------------
__device__ __align__(16) float d_h   [NMAX * HD];          // dinv-scaled xW1 (gather src)
__device__ __align__(16) float d_h2  [NMAX * HD];          // GCN accumulator
__device__ __align__(16) float d_hg  [NMAX * NHEADS * HD]; // GAT features [N,4,64]
__device__ __align__(16) float d_asrc[NMAX * NHEADS];
__device__ __align__(16) float d_adst[NMAX * NHEADS];
__device__ __align__(16) float d_den [NMAX * NHEADS];      // softmax denom -> 0.25/denom
__device__ __align__(16) float d_alpha[EMAX * NHEADS];     // per-edge exp values
__device__ __align__(16) float d_hga [NMAX * HD];          // GAT aggregation
__device__ __align__(16) float d_h3  [NMAX * HD];          // post-GAT features
__device__ __align__(16) float d_mean[NMAX * HD];          // SAGE sum accumulator
__device__ float d_cnt [NMAX];                             // in-degree (no self loops)
__device__ float d_dinv[NMAX];                             // rsqrt(deg+1)
__device__ int   d_row32[EMAX];
__device__ int   d_col32[EMAX];

// ---------------- helpers ----------------
__device__ __forceinline__ float lrelu(float x) { return x > 0.f ? x : 0.2f * x; }

// vector reduction (no return): 1 instruction for 4 lanes of atomicAdd
__device__ __forceinline__ void red_add_v4(float4* p, float4 v) {
    asm volatile("red.global.add.v4.f32 [%0], {%1, %2, %3, %4};"
                 :: "l"(p), "f"(v.x), "f"(v.y), "f"(v.z), "f"(v.w) : "memory");
}

// ---------------- kernels ----------------

// zero SAGE accumulator (float4) + cnt
__global__ void k_zero(int n) {
    int total = n * (HD / 4);
    int i = blockIdx.x * blockDim.x + threadIdx.x;
    if (i < total) reinterpret_cast<float4*>(d_mean)[i] = make_float4(0.f, 0.f, 0.f, 0.f);
    if (i < n) d_cnt[i] = 0.f;
}

// edge_index is INT32 (JAX x64 disabled). Copy + validate + in-degree count.
__global__ void k_edges32(const int* __restrict__ row0,
                          const int* __restrict__ col0, int e, int n) {
    int i = blockIdx.x * blockDim.x + threadIdx.x;
    if (i < e) {
        int r = row0[i];
        int c = col0[i];
        if ((unsigned)r >= (unsigned)n) r = 0;
        if ((unsigned)c >= (unsigned)n) c = 0;
        d_row32[i] = r;
        d_col32[i] = c;
        atomicAdd(&d_cnt[c], 1.f);
    }
}

__global__ void k_dinv(int n) {
    int i = blockIdx.x * blockDim.x + threadIdx.x;
    if (i < n) d_dinv[i] = rsqrtf(d_cnt[i] + 1.0f);
}

// GCN GEMM: v = dinv[row]*(x@W1); d_h = v (gather src); d_h2 = v (self-term init)
// JT=16 (4 consecutive cols per thread -> float4 W loads/stores), SG=16, RPT=4.
__global__ void k_gemm_gcn(const float* __restrict__ A, const float* __restrict__ W, int n) {
    const int K = FIN, JT = 16, SG = 16, RPT = 4;
    const int ROWS = SG * RPT;                       // 64
    __shared__ float xs[ROWS][K];
    int tid = threadIdx.x;
    int j0  = tid % JT;                              // col block: 4*j0 .. 4*j0+3
    int sg  = tid / JT;
    long long base = (long long)blockIdx.x * ROWS;
    // stage x rows (float4)
    {
        const int T4 = ROWS * (K / 4);               // 2048 float4s
        for (int i4 = tid; i4 < T4; i4 += 256) {
            long long row = base + i4 / (K / 4);
            int col4 = i4 % (K / 4);
            reinterpret_cast<float4*>(xs)[i4] =
                (row < n) ? __ldg(reinterpret_cast<const float4*>(A + row * K) + col4)
                          : make_float4(0.f, 0.f, 0.f, 0.f);
        }
    }
    __syncthreads();
    float4 acc[RPT];
#pragma unroll
    for (int r = 0; r < RPT; r++) acc[r] = make_float4(0.f, 0.f, 0.f, 0.f);
#pragma unroll 4
    for (int k = 0; k < K; k++) {
        float4 wv = __ldg(reinterpret_cast<const float4*>(W + k * HD) + j0);
#pragma unroll
        for (int r = 0; r < RPT; r++) {
            float xv = xs[sg * RPT + r][k];
            acc[r].x += xv * wv.x;
            acc[r].y += xv * wv.y;
            acc[r].z += xv * wv.z;
            acc[r].w += xv * wv.w;
        }
    }
#pragma unroll
    for (int r = 0; r < RPT; r++) {
        long long row = base + sg * RPT + r;
        if (row < n) {
            float dv = __ldg(&d_dinv[row]);
            float4 v = make_float4(acc[r].x * dv, acc[r].y * dv, acc[r].z * dv, acc[r].w * dv);
            reinterpret_cast<float4*>(d_h)[row * 16 + j0]  = v;
            reinterpret_cast<float4*>(d_h2)[row * 16 + j0] = v;
        }
    }
}

// GAT GEMM with fused GCN epilogue: xs = relu(dinv*h2 + b1); d_hg = xs @ Wg
// JT=64 (4 consecutive cols -> float4), SG=4, RPT=8, ROWS=32.
__global__ void k_gemm_gat(const float* __restrict__ Wg, const float* __restrict__ b1, int n) {
    const int K = HD, M = NHEADS * HD, JT = 64, SG = 4, RPT = 8;
    const int ROWS = SG * RPT;                       // 32
    __shared__ float xs[ROWS][K];
    int tid = threadIdx.x;
    int j0  = tid % JT;
    int sg  = tid / JT;
    long long base = (long long)blockIdx.x * ROWS;
    {
        const int T4 = ROWS * (K / 4);               // 512 float4s
        for (int i4 = tid; i4 < T4; i4 += 256) {
            long long row = base + i4 / (K / 4);
            int col4 = i4 % (K / 4);
            float4 v = make_float4(0.f, 0.f, 0.f, 0.f);
            if (row < n) {
                float4 h2v = __ldg(reinterpret_cast<const float4*>(d_h2) + row * 16 + col4);
                float4 bv  = __ldg(reinterpret_cast<const float4*>(b1) + col4);
                float dv = __ldg(&d_dinv[row]);
                v.x = fmaxf(dv * h2v.x + bv.x, 0.f);
                v.y = fmaxf(dv * h2v.y + bv.y, 0.f);
                v.z = fmaxf(dv * h2v.z + bv.z, 0.f);
                v.w = fmaxf(dv * h2v.w + bv.w, 0.f);
            }
            reinterpret_cast<float4*>(xs)[i4] = v;
        }
    }
    __syncthreads();
    float4 acc[RPT];
#pragma unroll
    for (int r = 0; r < RPT; r++) acc[r] = make_float4(0.f, 0.f, 0.f, 0.f);
#pragma unroll 4
    for (int k = 0; k < K; k++) {
        float4 wv = __ldg(reinterpret_cast<const float4*>(Wg + k * M) + j0);
#pragma unroll
        for (int r = 0; r < RPT; r++) {
            float xv = xs[sg * RPT + r][k];
            acc[r].x += xv * wv.x;
            acc[r].y += xv * wv.y;
            acc[r].z += xv * wv.z;
            acc[r].w += xv * wv.w;
        }
    }
#pragma unroll
    for (int r = 0; r < RPT; r++) {
        long long row = base + sg * RPT + r;
        if (row < n)
            reinterpret_cast<float4*>(d_hg)[row * 64 + j0] = acc[r];
    }
}

// GCN scatter (float4): h2[c] += h[r]
__global__ void k_gcn_scatter(int e) {
    int total = e * (HD / 4);
    int t = blockIdx.x * blockDim.x + threadIdx.x;
    if (t < total) {
        int ed = t >> 4, q = t & 15;
        int r = __ldg(&d_row32[ed]);
        int c = __ldg(&d_col32[ed]);
        float4 v = reinterpret_cast<const float4*>(d_h)[r * 16 + q];
        red_add_v4(&reinterpret_cast<float4*>(d_h2)[c * 16 + q], v);
    }
}

// per-(node,head) attention logits + denom init = exp(self logit)  (no max shift)
__global__ void k_att(const float* __restrict__ att_src,
                      const float* __restrict__ att_dst, int n) {
    long long w = (long long)(blockIdx.x * blockDim.x + threadIdx.x) >> 5;
    int lane = threadIdx.x & 31;
    long long total = (long long)n * NHEADS;
    long long stride = ((long long)gridDim.x * blockDim.x) >> 5;
    for (; w < total; w += stride) {
        int node = (int)(w >> 2), head = (int)(w & 3);
        const float* hgp = &d_hg[(long long)node * (NHEADS * HD) + head * HD];
        float s = hgp[lane] * __ldg(&att_src[head * HD + lane]) +
                  hgp[lane + 32] * __ldg(&att_src[head * HD + lane + 32]);
        float t = hgp[lane] * __ldg(&att_dst[head * HD + lane]) +
                  hgp[lane + 32] * __ldg(&att_dst[head * HD + lane + 32]);
#pragma unroll
        for (int o = 16; o; o >>= 1) {
            s += __shfl_down_sync(0xffffffffu, s, o);
            t += __shfl_down_sync(0xffffffffu, t, o);
        }
        if (lane == 0) {
            d_asrc[w] = s;
            d_adst[w] = t;
            d_den[w]  = expf(lrelu(s + t));   // self-loop term initializes denom
        }
    }
}

// per-edge ex = exp(lrelu(asrc[r]+adst[c])): store + accumulate into denom
__global__ void k_den_edges(int e) {
    int i = blockIdx.x * blockDim.x + threadIdx.x;
    if (i < e) {
        int r = d_row32[i], c = d_col32[i];
        const float4 as = reinterpret_cast<const float4*>(d_asrc)[r];
        const float4 ad = reinterpret_cast<const float4*>(d_adst)[c];
        float4 ex;
        ex.x = expf(lrelu(as.x + ad.x));
        ex.y = expf(lrelu(as.y + ad.y));
        ex.z = expf(lrelu(as.z + ad.z));
        ex.w = expf(lrelu(as.w + ad.w));
        reinterpret_cast<float4*>(d_alpha)[i] = ex;
        atomicAdd(&d_den[c * NHEADS + 0], ex.x);
        atomicAdd(&d_den[c * NHEADS + 1], ex.y);
        atomicAdd(&d_den[c * NHEADS + 2], ex.z);
        atomicAdd(&d_den[c * NHEADS + 3], ex.w);
    }
}

// hga init (float4): self contribution; also invert denom in place (0.25/den)
__global__ void k_hga_init(int n) {
    int total = n * (HD / 4);
    int t = blockIdx.x * blockDim.x + threadIdx.x;
    if (t < total) {
        int node = t >> 4, q = t & 15;
        const float4 as = reinterpret_cast<const float4*>(d_asrc)[node];
        const float4 ad = reinterpret_cast<const float4*>(d_adst)[node];
        const float4 dn = reinterpret_cast<const float4*>(d_den)[node];
        float4 inv = make_float4(0.25f / dn.x, 0.25f / dn.y, 0.25f / dn.z, 0.25f / dn.w);
        if (q == 0) reinterpret_cast<float4*>(d_den)[node] = inv;  // for gat_scatter
        float wx = expf(lrelu(as.x + ad.x)) * inv.x;
        float wy = expf(lrelu(as.y + ad.y)) * inv.y;
        float wz = expf(lrelu(as.z + ad.z)) * inv.z;
        float ww = expf(lrelu(as.w + ad.w)) * inv.w;
        const float4* hg4 = reinterpret_cast<const float4*>(d_hg);
        long long base = (long long)node * 64;
        float4 a = hg4[base + 0 * 16 + q];
        float4 b = hg4[base + 1 * 16 + q];
        float4 cc = hg4[base + 2 * 16 + q];
        float4 dd = hg4[base + 3 * 16 + q];
        float4 s;
        s.x = wx * a.x + wy * b.x + wz * cc.x + ww * dd.x;
        s.y = wx * a.y + wy * b.y + wz * cc.y + ww * dd.y;
        s.z = wx * a.z + wy * b.z + wz * cc.z + ww * dd.z;
        s.w = wx * a.w + wy * b.w + wz * cc.w + ww * dd.w;
        reinterpret_cast<float4*>(d_hga)[node * 16 + q] = s;
    }
}

// GAT scatter (float4): hga[c] += sum_h (ex[e,h] * 0.25/den[c,h]) * hg[r,h,:]
__global__ void k_gat_scatter(int e) {
    int total = e * (HD / 4);
    int t = blockIdx.x * blockDim.x + threadIdx.x;
    if (t < total) {
        int ed = t >> 4, q = t & 15;
        int r = __ldg(&d_row32[ed]);
        int c = __ldg(&d_col32[ed]);
        const float4 ex = reinterpret_cast<const float4*>(d_alpha)[ed];
        const float4 dn = reinterpret_cast<const float4*>(d_den)[c];   // 0.25/den
        float wx = ex.x * dn.x, wy = ex.y * dn.y, wz = ex.z * dn.z, ww = ex.w * dn.w;
        const float4* hg4 = reinterpret_cast<const float4*>(d_hg);
        long long base = (long long)r * 64;
        float4 a = hg4[base + 0 * 16 + q];
        float4 b = hg4[base + 1 * 16 + q];
        float4 cc = hg4[base + 2 * 16 + q];
        float4 dd = hg4[base + 3 * 16 + q];
        float4 s;
        s.x = wx * a.x + wy * b.x + wz * cc.x + ww * dd.x;
        s.y = wx * a.y + wy * b.y + wz * cc.y + ww * dd.y;
        s.z = wx * a.z + wy * b.z + wz * cc.z + ww * dd.z;
        s.w = wx * a.w + wy * b.w + wz * cc.w + ww * dd.w;
        red_add_v4(&reinterpret_cast<float4*>(d_hga)[c * 16 + q], s);
    }
}

// h3 = relu(hga + bg)
__global__ void k_relu_bg(const float* __restrict__ bg, int n) {
    int total = n * HD;
    int i = blockIdx.x * blockDim.x + threadIdx.x;
    if (i < total) d_h3[i] = fmaxf(d_hga[i] + bg[i & 63], 0.f);
}

// SAGE scatter (float4): mean[c] += h3[r]
__global__ void k_sage_scatter(int e) {
    int total = e * (HD / 4);
    int t = blockIdx.x * blockDim.x + threadIdx.x;
    if (t < total) {
        int ed = t >> 4, q = t & 15;
        int r = __ldg(&d_row32[ed]);
        int c = __ldg(&d_col32[ed]);
        float4 v = reinterpret_cast<const float4*>(d_h3)[r * 16 + q];
        red_add_v4(&reinterpret_cast<float4*>(d_mean)[c * 16 + q], v);
    }
}

// final: emb = mean@Wl + bl + h3@Wr ; MLP heads ; write outputs
__global__ void k_final(const float* __restrict__ Wl, const float* __restrict__ bl,
                        const float* __restrict__ Wr,
                        const float* __restrict__ a1w, const float* __restrict__ a1b,
                        const float* __restrict__ a2w, const float* __restrict__ a2b,
                        const float* __restrict__ r1w, const float* __restrict__ r1b,
                        const float* __restrict__ r2w, const float* __restrict__ r2b,
                        float* __restrict__ out_emb, float* __restrict__ out_an,
                        float* __restrict__ out_risk, int n) {
    __shared__ float Wls[HD * HD], Wrs[HD * HD];
    __shared__ float ms[4][HD], hs[4][HD], embs[4][HD];
    int tid = threadIdx.x;
    for (int i = tid; i < HD * HD; i += blockDim.x) {
        Wls[i] = Wl[i];
        Wrs[i] = Wr[i];
    }
    int sub = tid >> 6, j = tid & 63;
    int lane = tid & 31, wp = tid >> 5;
    int nd = wp >> 1, hd = wp & 1;
    for (long long base = (long long)blockIdx.x * 4; base < n;
         base += (long long)gridDim.x * 4) {
        int node = (int)base + sub;
        __syncthreads();
        if (node < n) {
            float inv = 1.f / fmaxf(d_cnt[node], 1.f);
            ms[sub][j] = d_mean[node * HD + j] * inv;
            hs[sub][j] = d_h3[node * HD + j];
        }
        __syncthreads();
        if (node < n) {
            float acc = bl[j];
#pragma unroll 16
            for (int k = 0; k < HD; k++)
                acc += ms[sub][k] * Wls[k * HD + j] + hs[sub][k] * Wrs[k * HD + j];
            embs[sub][j] = acc;
            out_emb[(long long)node * HD + j] = acc;
        }
        __syncthreads();
        int node2 = (int)base + nd;
        if (node2 < n) {
            const float* W1p = hd ? r1w : a1w;
            float acc = hd ? __ldg(&r1b[lane]) : __ldg(&a1b[lane]);
#pragma unroll 16
            for (int k = 0; k < HD; k++)
                acc += embs[nd][k] * __ldg(&W1p[k * 32 + lane]);
            acc = fmaxf(acc, 0.f) * (hd ? __ldg(&r2w[lane]) : __ldg(&a2w[lane]));
#pragma unroll
            for (int o = 16; o; o >>= 1) acc += __shfl_down_sync(0xffffffffu, acc, o);
            if (lane == 0) {
                float b2 = hd ? __ldg(&r2b[0]) : __ldg(&a2b[0]);
                float v = 1.f / (1.f + expf(-(acc + b2)));
                if (hd) out_risk[node2] = v;
                else    out_an[node2] = v;
            }
        }
    }
}

// ---------------- launcher ----------------
extern "C" void kernel_launch(void* const* d_in, const int* in_sizes, int n_in,
                              void* d_out, int out_size) {
    const float* x   = (const float*)d_in[0];
    const int*   ei  = (const int*)d_in[1];   // int32 (JAX x64 disabled)
    const float* W1  = (const float*)d_in[2];
    const float* b1  = (const float*)d_in[3];
    const float* Wg  = (const float*)d_in[4];
    const float* ats = (const float*)d_in[5];
    const float* atd = (const float*)d_in[6];
    const float* bg  = (const float*)d_in[7];
    const float* Wl  = (const float*)d_in[8];
    const float* bl  = (const float*)d_in[9];
    const float* Wr  = (const float*)d_in[10];
    const float* a1w = (const float*)d_in[11];
    const float* a1b = (const float*)d_in[12];
    const float* a2w = (const float*)d_in[13];
    const float* a2b = (const float*)d_in[14];
    const float* r1w = (const float*)d_in[15];
    const float* r1b = (const float*)d_in[16];
    const float* r2w = (const float*)d_in[17];
    const float* r2b = (const float*)d_in[18];

    int n = in_sizes[0] / FIN;
    int e = in_sizes[1] / 2;
    const int* row0 = ei;
    const int* col0 = ei + e;

    float* out      = (float*)d_out;
    float* out_emb  = out;
    float* out_an   = out + (long long)n * HD;
    float* out_risk = out_an + n;

    const int B = 256;
    int gNH = (n * HD + B - 1) / B;
    int gN  = (n + B - 1) / B;
    int gE  = (e + B - 1) / B;
    int gE4 = (e * (HD / 4) + B - 1) / B;
    int gN4 = (n * (HD / 4) + B - 1) / B;

    // preprocessing
    k_zero<<<gN4, B>>>(n);
    k_edges32<<<gE, B>>>(row0, col0, e, n);
    k_dinv<<<gN, B>>>(n);

    // GCN
    k_gemm_gcn<<<(n + 63) / 64, 256>>>(x, W1, n);
    k_gcn_scatter<<<gE4, B>>>(e);

    // GAT (relu_b1 fused into GEMM staging)
    k_gemm_gat<<<(n + 31) / 32, 256>>>(Wg, b1, n);
    k_att<<<(n * NHEADS * 32 + B - 1) / B, B>>>(ats, atd, n);
    k_den_edges<<<gE, B>>>(e);
    k_hga_init<<<gN4, B>>>(n);
    k_gat_scatter<<<gE4, B>>>(e);
    k_relu_bg<<<gNH, B>>>(bg, n);

    // SAGE
    k_sage_scatter<<<gE4, B>>>(e);

    // emb + heads
    k_final<<<(n + 3) / 4, B>>>(Wl, bl, Wr, a1w, a1b, a2w, a2b,
                                r1w, r1b, r2w, r2b,
                                out_emb, out_an, out_risk, n);
}